// round 2
// baseline (speedup 1.0000x reference)
#include <cuda_runtime.h>
#include <math.h>

#define KCOMP 1024
#define DDIM  6
#define BPTS  16384
#define KS    8            // K slices
#define KC    (KCOMP/KS)   // 128 components per slice
#define NCOEF 28           // 1 const + 6 linear + 21 quadratic
#define TPB   256

// coefficients, duplicated per lane-pair: [k][28][2] floats
__device__ __align__(16) float g_coefs[KCOMP * NCOEF * 2];
// per-slice partial (m, s) in log2 domain: [KS][B]
__device__ float2 g_part[KS * BPTS];

// ---------- packed f32x2 helpers ----------
__device__ __forceinline__ unsigned long long pk2(float lo, float hi) {
    unsigned long long r;
    asm("mov.b64 %0, {%1, %2};" : "=l"(r) : "f"(lo), "f"(hi));
    return r;
}
__device__ __forceinline__ void upk2(unsigned long long v, float& lo, float& hi) {
    asm("mov.b64 {%0, %1}, %2;" : "=f"(lo), "=f"(hi) : "l"(v));
}
__device__ __forceinline__ unsigned long long fma2(unsigned long long a,
                                                   unsigned long long b,
                                                   unsigned long long c) {
    unsigned long long d;
    asm("fma.rn.f32x2 %0, %1, %2, %3;" : "=l"(d) : "l"(a), "l"(b), "l"(c));
    return d;
}
__device__ __forceinline__ unsigned long long add2(unsigned long long a,
                                                   unsigned long long b) {
    unsigned long long d;
    asm("add.rn.f32x2 %0, %1, %2;" : "=l"(d) : "l"(a), "l"(b));
    return d;
}
__device__ __forceinline__ float ex2(float x) {
    float r;
    asm("ex2.approx.f32 %0, %1;" : "=f"(r) : "f"(x));
    return r;
}

// ---------- kernel 1: per-component Cholesky -> inverse -> feature coefs ----------
__global__ void gmm_precompute(const float* __restrict__ means,
                               const float* __restrict__ covs,
                               const float* __restrict__ weights) {
    int k = blockIdx.x * blockDim.x + threadIdx.x;
    if (k >= KCOMP) return;

    float C[DDIM][DDIM];
#pragma unroll
    for (int i = 0; i < DDIM; i++)
#pragma unroll
        for (int j = 0; j < DDIM; j++)
            C[i][j] = covs[k * DDIM * DDIM + i * DDIM + j];

    // Cholesky: C = L L^T (lower)
    float L[DDIM][DDIM];
#pragma unroll
    for (int j = 0; j < DDIM; j++) {
        float s = C[j][j];
#pragma unroll
        for (int p = 0; p < DDIM; p++)
            if (p < j) s -= L[j][p] * L[j][p];
        float d = sqrtf(s);
        L[j][j] = d;
        float inv = 1.0f / d;
#pragma unroll
        for (int i = 0; i < DDIM; i++) {
            if (i > j) {
                float t = C[i][j];
#pragma unroll
                for (int p = 0; p < DDIM; p++)
                    if (p < j) t -= L[i][p] * L[j][p];
                L[i][j] = t * inv;
            }
        }
    }

    float logdet = 0.0f;
#pragma unroll
    for (int j = 0; j < DDIM; j++) logdet += logf(L[j][j]);
    logdet *= 2.0f;

    // invert L (lower triangular)
    float Li[DDIM][DDIM];
#pragma unroll
    for (int j = 0; j < DDIM; j++) {
        Li[j][j] = 1.0f / L[j][j];
#pragma unroll
        for (int i = 0; i < DDIM; i++) {
            if (i > j) {
                float t = 0.0f;
#pragma unroll
                for (int p = 0; p < DDIM; p++)
                    if (p >= j && p < i) t += L[i][p] * Li[p][j];
                Li[i][j] = -t / L[i][i];
            }
        }
    }

    // A = Sigma^{-1} = Li^T Li
    float A[DDIM][DDIM];
#pragma unroll
    for (int i = 0; i < DDIM; i++)
#pragma unroll
        for (int j = 0; j < DDIM; j++) {
            if (j >= i) {
                float s = 0.0f;
#pragma unroll
                for (int p = 0; p < DDIM; p++)
                    if (p >= j) s += Li[p][i] * Li[p][j];
                A[i][j] = s;
            }
        }
#pragma unroll
    for (int i = 0; i < DDIM; i++)
#pragma unroll
        for (int j = 0; j < DDIM; j++)
            if (j < i) A[i][j] = A[j][i];

    float mu[DDIM];
#pragma unroll
    for (int i = 0; i < DDIM; i++) mu[i] = means[k * DDIM + i];
    float v[DDIM];
    float muAmu = 0.0f;
#pragma unroll
    for (int i = 0; i < DDIM; i++) {
        float s = 0.0f;
#pragma unroll
        for (int j = 0; j < DDIM; j++) s += A[i][j] * mu[j];
        v[i] = s;
        muAmu += s * mu[i];
    }

    const float LOG2E = 1.4426950408889634f;
    const float LN2PI = 1.8378770664093453f;  // log(2*pi)
    float g0 = logf(weights[k]) - 0.5f * (DDIM * LN2PI + logdet + muAmu);

    float* dst = g_coefs + k * (NCOEF * 2);
    dst[0] = dst[1] = g0 * LOG2E;
    int idx = 1;
#pragma unroll
    for (int i = 0; i < DDIM; i++) {
        float cf = v[i] * LOG2E;
        dst[2 * idx] = dst[2 * idx + 1] = cf;
        idx++;
    }
#pragma unroll
    for (int i = 0; i < DDIM; i++)
#pragma unroll
        for (int j = 0; j < DDIM; j++) {
            if (j >= i) {
                float cf = (i == j) ? (-0.5f * A[i][i]) : (-A[i][j]);
                cf *= LOG2E;
                dst[2 * idx] = dst[2 * idx + 1] = cf;
                idx++;
            }
        }
}

// ---------- online logsumexp update (log2 domain) ----------
__device__ __forceinline__ void lse_upd(float t, float& m, float& s) {
    float mn = fmaxf(m, t);
    s = s * ex2(m - mn) + ex2(t - mn);
    m = mn;
}

// ---------- kernel 2: main GEMM-like pass, 4 points/thread, f32x2 packed ----------
__global__ void __launch_bounds__(TPB) gmm_main(const float* __restrict__ x) {
    __shared__ __align__(16) float s_coefs[KC * NCOEF * 2];  // 28672 B

    const int tid = threadIdx.x;
    {
        const float4* src = (const float4*)(g_coefs + blockIdx.y * (KC * NCOEF * 2));
        float4* dst = (float4*)s_coefs;
#pragma unroll
        for (int i = 0; i < (KC * NCOEF * 2) / 4 / TPB; i++)
            dst[tid + i * TPB] = src[tid + i * TPB];
        __syncthreads();
    }

    const int p0 = blockIdx.x * (TPB * 4) + tid * 4;

    float xv[4][DDIM];
#pragma unroll
    for (int p = 0; p < 4; p++)
#pragma unroll
        for (int d = 0; d < DDIM; d++)
            xv[p][d] = x[(p0 + p) * DDIM + d];

    // features: [0..5] x_i ; [6..26] x_i*x_j (i<=j). Pair A = points 0,1; B = 2,3.
    unsigned long long phiA[27], phiB[27];
#pragma unroll
    for (int d = 0; d < DDIM; d++) {
        phiA[d] = pk2(xv[0][d], xv[1][d]);
        phiB[d] = pk2(xv[2][d], xv[3][d]);
    }
    {
        int f = 6;
#pragma unroll
        for (int i = 0; i < DDIM; i++)
#pragma unroll
            for (int j = 0; j < DDIM; j++) {
                if (j >= i) {
                    phiA[f] = pk2(xv[0][i] * xv[0][j], xv[1][i] * xv[1][j]);
                    phiB[f] = pk2(xv[2][i] * xv[2][j], xv[3][i] * xv[3][j]);
                    f++;
                }
            }
    }

    float m0 = -1e30f, m1 = -1e30f, m2 = -1e30f, m3 = -1e30f;
    float s0 = 0.0f, s1 = 0.0f, s2 = 0.0f, s3 = 0.0f;

    const unsigned long long* cs = (const unsigned long long*)s_coefs;
    for (int k = 0; k < KC; k++) {
        const unsigned long long* cp = cs + k * NCOEF;
        unsigned long long a0 = cp[0], a1 = 0ull;  // acc init with constant term
        unsigned long long b0 = cp[0], b1 = 0ull;
#pragma unroll
        for (int q = 0; q < 27; q++) {
            unsigned long long c = cp[q + 1];
            if (q & 1) {
                a1 = fma2(phiA[q], c, a1);
                b1 = fma2(phiB[q], c, b1);
            } else {
                a0 = fma2(phiA[q], c, a0);
                b0 = fma2(phiB[q], c, b0);
            }
        }
        unsigned long long ta = add2(a0, a1);
        unsigned long long tb = add2(b0, b1);
        float t0, t1, t2, t3;
        upk2(ta, t0, t1);
        upk2(tb, t2, t3);
        lse_upd(t0, m0, s0);
        lse_upd(t1, m1, s1);
        lse_upd(t2, m2, s2);
        lse_upd(t3, m3, s3);
    }

    float2* gp = g_part + blockIdx.y * BPTS;
    gp[p0 + 0] = make_float2(m0, s0);
    gp[p0 + 1] = make_float2(m1, s1);
    gp[p0 + 2] = make_float2(m2, s2);
    gp[p0 + 3] = make_float2(m3, s3);
}

// ---------- kernel 3: combine the KS slice partials ----------
__global__ void gmm_combine(float* __restrict__ out) {
    int b = blockIdx.x * blockDim.x + threadIdx.x;
    if (b >= BPTS) return;
    float m = -1e30f, s = 0.0f;
#pragma unroll
    for (int ks = 0; ks < KS; ks++) {
        float2 p = g_part[ks * BPTS + b];
        float mn = fmaxf(m, p.x);
        s = s * ex2(m - mn) + p.y * ex2(p.x - mn);
        m = mn;
    }
    const float LN2 = 0.6931471805599453f;
    out[b] = LN2 * m + logf(s);
}

extern "C" void kernel_launch(void* const* d_in, const int* in_sizes, int n_in,
                              void* d_out, int out_size) {
    const float* x       = (const float*)d_in[0];
    const float* means   = (const float*)d_in[1];
    const float* covs    = (const float*)d_in[2];
    const float* weights = (const float*)d_in[3];
    float* out = (float*)d_out;

    gmm_precompute<<<KCOMP / 256, 256>>>(means, covs, weights);
    dim3 grid(BPTS / (TPB * 4), KS);
    gmm_main<<<grid, TPB>>>(x);
    gmm_combine<<<BPTS / 256, 256>>>(out);
}

// round 4
// speedup vs baseline: 1.1730x; 1.1730x over previous
#include <cuda_runtime.h>
#include <math.h>

#define KCOMP 1024
#define DDIM  6
#define BPTS  16384
#define KS    8            // K slices
#define KC    (KCOMP/KS)   // 128 components per slice
#define NCOEF 28           // 1 const + 6 linear + 21 quadratic
#define TPB   256

// coefficients, duplicated per lane-pair: [k][28][2] floats
__device__ __align__(16) float g_coefs[KCOMP * NCOEF * 2];
// per-slice partial (m, s) in log2 domain: [KS][B]
__device__ float2 g_part[KS * BPTS];

// ---------- packed f32x2 helpers ----------
__device__ __forceinline__ unsigned long long pk2(float lo, float hi) {
    unsigned long long r;
    asm("mov.b64 %0, {%1, %2};" : "=l"(r) : "f"(lo), "f"(hi));
    return r;
}
__device__ __forceinline__ void upk2(unsigned long long v, float& lo, float& hi) {
    asm("mov.b64 {%0, %1}, %2;" : "=f"(lo), "=f"(hi) : "l"(v));
}
__device__ __forceinline__ unsigned long long fma2(unsigned long long a,
                                                   unsigned long long b,
                                                   unsigned long long c) {
    unsigned long long d;
    asm("fma.rn.f32x2 %0, %1, %2, %3;" : "=l"(d) : "l"(a), "l"(b), "l"(c));
    return d;
}
__device__ __forceinline__ float ex2(float x) {
    float r;
    asm("ex2.approx.f32 %0, %1;" : "=f"(r) : "f"(x));
    return r;
}

// ---------- kernel 1: per-component Cholesky -> inverse -> feature coefs ----------
// Fast-math version: rsqrt-based Cholesky, reciprocal multiplies, single __logf.
__global__ void gmm_precompute(const float* __restrict__ means,
                               const float* __restrict__ covs,
                               const float* __restrict__ weights) {
    int k = blockIdx.x * blockDim.x + threadIdx.x;
    if (k >= KCOMP) return;

    float C[DDIM][DDIM];
#pragma unroll
    for (int i = 0; i < DDIM; i++)
#pragma unroll
        for (int j = 0; j < DDIM; j++)
            C[i][j] = covs[k * DDIM * DDIM + i * DDIM + j];

    // Cholesky: C = L L^T (lower), with rsqrt (MUFU) instead of sqrt+div
    float L[DDIM][DDIM];
    float invd[DDIM];
    float diagprod = 1.0f;
#pragma unroll
    for (int j = 0; j < DDIM; j++) {
        float s = C[j][j];
#pragma unroll
        for (int p = 0; p < DDIM; p++)
            if (p < j) s -= L[j][p] * L[j][p];
        float rd = rsqrtf(s);
        float d = s * rd;          // sqrt(s)
        L[j][j] = d;
        invd[j] = rd;
        diagprod *= d;
#pragma unroll
        for (int i = 0; i < DDIM; i++) {
            if (i > j) {
                float t = C[i][j];
#pragma unroll
                for (int p = 0; p < DDIM; p++)
                    if (p < j) t -= L[i][p] * L[j][p];
                L[i][j] = t * rd;
            }
        }
    }

    float logdet = 2.0f * __logf(diagprod);

    // invert L (lower triangular) via reciprocal multiplies
    float Li[DDIM][DDIM];
#pragma unroll
    for (int j = 0; j < DDIM; j++) {
        Li[j][j] = invd[j];
#pragma unroll
        for (int i = 0; i < DDIM; i++) {
            if (i > j) {
                float t = 0.0f;
#pragma unroll
                for (int p = 0; p < DDIM; p++)
                    if (p >= j && p < i) t += L[i][p] * Li[p][j];
                Li[i][j] = -t * invd[i];
            }
        }
    }

    // A = Sigma^{-1} = Li^T Li
    float A[DDIM][DDIM];
#pragma unroll
    for (int i = 0; i < DDIM; i++)
#pragma unroll
        for (int j = 0; j < DDIM; j++) {
            if (j >= i) {
                float s = 0.0f;
#pragma unroll
                for (int p = 0; p < DDIM; p++)
                    if (p >= j) s += Li[p][i] * Li[p][j];
                A[i][j] = s;
            }
        }
#pragma unroll
    for (int i = 0; i < DDIM; i++)
#pragma unroll
        for (int j = 0; j < DDIM; j++)
            if (j < i) A[i][j] = A[j][i];

    float mu[DDIM];
#pragma unroll
    for (int i = 0; i < DDIM; i++) mu[i] = means[k * DDIM + i];
    float v[DDIM];
    float muAmu = 0.0f;
#pragma unroll
    for (int i = 0; i < DDIM; i++) {
        float s = 0.0f;
#pragma unroll
        for (int j = 0; j < DDIM; j++) s += A[i][j] * mu[j];
        v[i] = s;
        muAmu += s * mu[i];
    }

    const float LOG2E = 1.4426950408889634f;
    const float LN2PI = 1.8378770664093453f;  // log(2*pi)
    float g0 = __logf(weights[k]) - 0.5f * (DDIM * LN2PI + logdet + muAmu);

    float* dst = g_coefs + k * (NCOEF * 2);
    dst[0] = dst[1] = g0 * LOG2E;
    int idx = 1;
#pragma unroll
    for (int i = 0; i < DDIM; i++) {
        float cf = v[i] * LOG2E;
        dst[2 * idx] = dst[2 * idx + 1] = cf;
        idx++;
    }
#pragma unroll
    for (int i = 0; i < DDIM; i++)
#pragma unroll
        for (int j = 0; j < DDIM; j++) {
            if (j >= i) {
                float cf = (i == j) ? (-0.5f * A[i][i]) : (-A[i][j]);
                cf *= LOG2E;
                dst[2 * idx] = dst[2 * idx + 1] = cf;
                idx++;
            }
        }
}

// ---------- kernel 2: main pass, 4 points/thread, f32x2 packed, k unrolled by 2 ----------
__global__ void __launch_bounds__(TPB) gmm_main(const float* __restrict__ x) {
    __shared__ __align__(16) float s_coefs[KC * NCOEF * 2];  // 28672 B

    const int tid = threadIdx.x;
    {
        const float4* src = (const float4*)(g_coefs + blockIdx.y * (KC * NCOEF * 2));
        float4* dst = (float4*)s_coefs;
#pragma unroll
        for (int i = 0; i < (KC * NCOEF * 2) / 4 / TPB; i++)
            dst[tid + i * TPB] = src[tid + i * TPB];
        __syncthreads();
    }

    const int p0 = blockIdx.x * (TPB * 4) + tid * 4;

    float xv[4][DDIM];
#pragma unroll
    for (int p = 0; p < 4; p++)
#pragma unroll
        for (int d = 0; d < DDIM; d++)
            xv[p][d] = x[(p0 + p) * DDIM + d];

    // features: [0..5] x_i ; [6..26] x_i*x_j (i<=j). Pair A = points 0,1; B = 2,3.
    unsigned long long phiA[27], phiB[27];
#pragma unroll
    for (int d = 0; d < DDIM; d++) {
        phiA[d] = pk2(xv[0][d], xv[1][d]);
        phiB[d] = pk2(xv[2][d], xv[3][d]);
    }
    {
        int f = 6;
#pragma unroll
        for (int i = 0; i < DDIM; i++)
#pragma unroll
            for (int j = 0; j < DDIM; j++) {
                if (j >= i) {
                    phiA[f] = pk2(xv[0][i] * xv[0][j], xv[1][i] * xv[1][j]);
                    phiB[f] = pk2(xv[2][i] * xv[2][j], xv[3][i] * xv[3][j]);
                    f++;
                }
            }
    }

    float m0 = -1e30f, m1 = -1e30f, m2 = -1e30f, m3 = -1e30f;
    float s0 = 0.0f, s1 = 0.0f, s2 = 0.0f, s3 = 0.0f;

    const ulonglong2* cs = (const ulonglong2*)s_coefs;
    for (int k = 0; k < KC; k += 2) {
        const ulonglong2* c0 = cs + k * (NCOEF / 2);
        const ulonglong2* c1 = c0 + (NCOEF / 2);

        // single-accumulator chains, init with constant term (element 0)
        unsigned long long aA, aB, bA, bB;
        {
            ulonglong2 w0 = c0[0];     // .x = const, .y = feature 0 coef
            ulonglong2 w1 = c1[0];
            aA = fma2(phiA[0], w0.y, w0.x);
            aB = fma2(phiB[0], w0.y, w0.x);
            bA = fma2(phiA[0], w1.y, w1.x);
            bB = fma2(phiB[0], w1.y, w1.x);
        }
#pragma unroll
        for (int i = 1; i < 14; i++) {
            ulonglong2 w0 = c0[i];     // .x = feature 2i-1, .y = feature 2i
            ulonglong2 w1 = c1[i];
            int q0 = 2 * i - 1, q1 = 2 * i;
            aA = fma2(phiA[q0], w0.x, aA);
            aB = fma2(phiB[q0], w0.x, aB);
            bA = fma2(phiA[q0], w1.x, bA);
            bB = fma2(phiB[q0], w1.x, bB);
            aA = fma2(phiA[q1], w0.y, aA);
            aB = fma2(phiB[q1], w0.y, aB);
            bA = fma2(phiA[q1], w1.y, bA);
            bB = fma2(phiB[q1], w1.y, bB);
        }

        float t0, t1, t2, t3, u0, u1, u2, u3;
        upk2(aA, t0, t1);
        upk2(aB, t2, t3);
        upk2(bA, u0, u1);
        upk2(bB, u2, u3);

        // batched online lse over the two components
        {
            float mn = fmaxf(m0, fmaxf(t0, u0));
            s0 = fmaf(s0, ex2(m0 - mn), ex2(t0 - mn) + ex2(u0 - mn));
            m0 = mn;
        }
        {
            float mn = fmaxf(m1, fmaxf(t1, u1));
            s1 = fmaf(s1, ex2(m1 - mn), ex2(t1 - mn) + ex2(u1 - mn));
            m1 = mn;
        }
        {
            float mn = fmaxf(m2, fmaxf(t2, u2));
            s2 = fmaf(s2, ex2(m2 - mn), ex2(t2 - mn) + ex2(u2 - mn));
            m2 = mn;
        }
        {
            float mn = fmaxf(m3, fmaxf(t3, u3));
            s3 = fmaf(s3, ex2(m3 - mn), ex2(t3 - mn) + ex2(u3 - mn));
            m3 = mn;
        }
    }

    float2* gp = g_part + blockIdx.y * BPTS;
    gp[p0 + 0] = make_float2(m0, s0);
    gp[p0 + 1] = make_float2(m1, s1);
    gp[p0 + 2] = make_float2(m2, s2);
    gp[p0 + 3] = make_float2(m3, s3);
}

// ---------- kernel 3: combine the KS slice partials ----------
__global__ void gmm_combine(float* __restrict__ out) {
    int b = blockIdx.x * blockDim.x + threadIdx.x;
    if (b >= BPTS) return;
    float m = -1e30f, s = 0.0f;
#pragma unroll
    for (int ks = 0; ks < KS; ks++) {
        float2 p = g_part[ks * BPTS + b];
        float mn = fmaxf(m, p.x);
        s = s * ex2(m - mn) + p.y * ex2(p.x - mn);
        m = mn;
    }
    const float LN2 = 0.6931471805599453f;
    out[b] = LN2 * m + __logf(s);
}

extern "C" void kernel_launch(void* const* d_in, const int* in_sizes, int n_in,
                              void* d_out, int out_size) {
    const float* x       = (const float*)d_in[0];
    const float* means   = (const float*)d_in[1];
    const float* covs    = (const float*)d_in[2];
    const float* weights = (const float*)d_in[3];
    float* out = (float*)d_out;

    gmm_precompute<<<KCOMP / 128, 128>>>(means, covs, weights);
    dim3 grid(BPTS / (TPB * 4), KS);
    gmm_main<<<grid, TPB>>>(x);
    gmm_combine<<<BPTS / 256, 256>>>(out);
}